// round 17
// baseline (speedup 1.0000x reference)
#include <cuda_runtime.h>
#include <cuda_fp16.h>
#include <cstdint>

#define N_NODES 200000
#define SEGS    16384
#define NTILES  ((N_NODES + 127) / 128)   // 1563
#define FEAPAD  (NTILES * 128)            // 200064 rows (padded)
#define HEADS   4
#define LH2     68     // smem row stride in half2 units (272 B)
#define SLOPE   0.01f

// ---------------- device scratch ----------------
__device__ float    g_denom[SEGS * HEADS];
__device__ unsigned g_pre1[HEADS * SEGS * 64];        // fp16x2: W1R . cry per segment
__device__ float    g_H[(size_t)HEADS * SEGS * 128];  // Σ e_n h_n per segment
__device__ __align__(16) unsigned g_feah[(size_t)FEAPAD * 64];  // fea as fp16x2, padded

// ---------------- helpers ----------------
__device__ __forceinline__ unsigned h2pack(float a, float b) {
    unsigned r;
    asm("cvt.rn.f16x2.f32 %0, %2, %1;" : "=r"(r) : "f"(a), "f"(b));
    return r;  // lo = a, hi = b
}

__device__ __forceinline__ void mma_f16(float c[4], const unsigned a[4], const unsigned b[2]) {
    asm volatile(
        "mma.sync.aligned.m16n8k16.row.col.f32.f16.f16.f32 "
        "{%0,%1,%2,%3}, {%4,%5,%6,%7}, {%8,%9}, {%0,%1,%2,%3};\n"
        : "+f"(c[0]), "+f"(c[1]), "+f"(c[2]), "+f"(c[3])
        : "r"(a[0]), "r"(a[1]), "r"(a[2]), "r"(a[3]), "r"(b[0]), "r"(b[1]));
}

__device__ __forceinline__ void ldsm_x4(unsigned &r0, unsigned &r1, unsigned &r2, unsigned &r3,
                                        unsigned addr) {
    asm volatile("ldmatrix.sync.aligned.m8n8.x4.shared.b16 {%0,%1,%2,%3}, [%4];"
                 : "=r"(r0), "=r"(r1), "=r"(r2), "=r"(r3) : "r"(addr));
}

__device__ __forceinline__ void cpa16(unsigned saddr, const void* g) {
    asm volatile("cp.async.ca.shared.global [%0], [%1], 16;" :: "r"(saddr), "l"(g) : "memory");
}

// async-load a 128x128 fp16 tile from g_feah, then commit
__device__ __forceinline__ void load_tile_async(unsigned sAaddr, const unsigned* __restrict__ src,
                                                int tid) {
#pragma unroll
    for (int i = 0; i < 8; i++) {
        int v = i * 256 + tid;
        int r = v >> 4, ch = v & 15;
        cpa16(sAaddr + (unsigned)(r * 272 + ch * 16), src + (size_t)r * 64 + ch * 4);
    }
    asm volatile("cp.async.commit_group;" ::: "memory");
}

// 128x128x128 GEMM; 8 warps (4x2), warp tile 32x64, ldmatrix.x4 feed.
__device__ __forceinline__ void gemm128h(const unsigned* sA, const unsigned* sB,
                                         float (&acc)[2][8][4],
                                         int warpRow, int warpCol, int lane) {
    const unsigned sAb = (unsigned)__cvta_generic_to_shared(sA);
    const unsigned sBb = (unsigned)__cvta_generic_to_shared(sB);
    const int l15 = lane & 15, l7 = lane & 7;
    unsigned aAddr[2], bAddr[4];
#pragma unroll
    for (int mt = 0; mt < 2; mt++)
        aAddr[mt] = sAb + (unsigned)((warpRow * 32 + mt * 16 + l15) * 272 + (lane >> 4) * 16);
#pragma unroll
    for (int p = 0; p < 4; p++)
        bAddr[p] = sBb + (unsigned)((warpCol * 64 + p * 16 + l7 + ((lane & 16) >> 1)) * 272
                                    + ((lane >> 3) & 1) * 16);
#pragma unroll
    for (int ks = 0; ks < 8; ks++) {
        unsigned a[2][4], b[8][2];
#pragma unroll
        for (int mt = 0; mt < 2; mt++) {
            ldsm_x4(a[mt][0], a[mt][1], a[mt][2], a[mt][3], aAddr[mt]);
            aAddr[mt] += 32;
        }
#pragma unroll
        for (int p = 0; p < 4; p++) {
            ldsm_x4(b[2 * p][0], b[2 * p][1], b[2 * p + 1][0], b[2 * p + 1][1], bAddr[p]);
            bAddr[p] += 32;
        }
#pragma unroll
        for (int mt = 0; mt < 2; mt++)
#pragma unroll
            for (int nt = 0; nt < 8; nt++)
                mma_f16(acc[mt][nt], a[mt], b[nt]);
    }
}

// 128x64x128 GEMM (N=64); 8 warps (4x2), warp tile 32x32.
__device__ __forceinline__ void gemm64h(const unsigned* sA, const unsigned* sB,
                                        float (&acc)[2][4][4],
                                        int warpRow, int warpCol, int lane) {
    const unsigned sAb = (unsigned)__cvta_generic_to_shared(sA);
    const unsigned sBb = (unsigned)__cvta_generic_to_shared(sB);
    const int l15 = lane & 15, l7 = lane & 7;
    unsigned aAddr[2], bAddr[2];
#pragma unroll
    for (int mt = 0; mt < 2; mt++)
        aAddr[mt] = sAb + (unsigned)((warpRow * 32 + mt * 16 + l15) * 272 + (lane >> 4) * 16);
#pragma unroll
    for (int p = 0; p < 2; p++)
        bAddr[p] = sBb + (unsigned)((warpCol * 32 + p * 16 + l7 + ((lane & 16) >> 1)) * 272
                                    + ((lane >> 3) & 1) * 16);
#pragma unroll
    for (int ks = 0; ks < 8; ks++) {
        unsigned a[2][4], b[4][2];
#pragma unroll
        for (int mt = 0; mt < 2; mt++) {
            ldsm_x4(a[mt][0], a[mt][1], a[mt][2], a[mt][3], aAddr[mt]);
            aAddr[mt] += 32;
        }
#pragma unroll
        for (int p = 0; p < 2; p++) {
            ldsm_x4(b[2 * p][0], b[2 * p][1], b[2 * p + 1][0], b[2 * p + 1][1], bAddr[p]);
            bAddr[p] += 32;
        }
#pragma unroll
        for (int mt = 0; mt < 2; mt++)
#pragma unroll
            for (int nt = 0; nt < 4; nt++)
                mma_f16(acc[mt][nt], a[mt], b[nt]);
    }
}

__device__ __forceinline__ void load_w_h(unsigned* dst, const float* __restrict__ src,
                                         int srcStride, int tid) {
#pragma unroll
    for (int i = 0; i < 16; i++) {
        int v = i * 256 + tid;
        int r = v >> 5, c4 = v & 31;
        float4 val = *reinterpret_cast<const float4*>(src + (size_t)r * srcStride + c4 * 4);
        uint2 u = make_uint2(h2pack(val.x, val.y), h2pack(val.z, val.w));
        *reinterpret_cast<uint2*>(dst + r * LH2 + c4 * 2) = u;
    }
}

// 64-row weight tile
__device__ __forceinline__ void load_w_h64(unsigned* dst, const float* __restrict__ src,
                                           int srcStride, int tid) {
#pragma unroll
    for (int i = 0; i < 8; i++) {
        int v = i * 256 + tid;
        int r = v >> 5, c4 = v & 31;
        float4 val = *reinterpret_cast<const float4*>(src + (size_t)r * srcStride + c4 * 4);
        uint2 u = make_uint2(h2pack(val.x, val.y), h2pack(val.z, val.w));
        *reinterpret_cast<uint2*>(dst + r * LH2 + c4 * 2) = u;
    }
}

// ---------------- kernel 0 (merged): pre-GEMM blocks + init blocks ----------
// blocks [0,512): pre1[h][s] = W1R . cry[s];  blocks [512,2048): fea->fp16,
// zero g_H, zero denom.
__global__ void __launch_bounds__(256, 2)
k_prep(const float* __restrict__ cry, const float* __restrict__ Wa1,
       const float* __restrict__ fea) {
    const int b = blockIdx.x;
    const int tid = threadIdx.x;

    if (b >= 512) {
        // ---- init part ----
        int i = (b - 512) * 256 + tid;
        int stride = 1536 * 256;
        const int totF4 = FEAPAD * 32;
        const int nF4   = N_NODES * 32;
        for (int j = i; j < totF4; j += stride) {
            float4 v = make_float4(0.f, 0.f, 0.f, 0.f);
            if (j < nF4) v = reinterpret_cast<const float4*>(fea)[j];
            reinterpret_cast<uint2*>(g_feah)[j] =
                make_uint2(h2pack(v.x, v.y), h2pack(v.z, v.w));
        }
        int nH4 = (HEADS * SEGS * 128) >> 2;
        for (int j = i; j < nH4; j += stride)
            reinterpret_cast<float4*>(g_H)[j] = make_float4(0.f, 0.f, 0.f, 0.f);
        for (int j = i; j < SEGS * HEADS; j += stride) g_denom[j] = 0.f;
        return;
    }

    // ---- pre part ----
    extern __shared__ unsigned smem_u[];
    unsigned* sA = smem_u;              // cry tile
    unsigned* sB = sA + 128 * LH2;      // W1R

    const int lane = tid & 31;
    const int warp = tid >> 5;
    const int warpRow = warp >> 1, warpCol = warp & 1;
    const int g = lane >> 2, t = lane & 3;
    const int h  = b >> 7;
    const int s0 = (b & 127) * 128;

    load_w_h(sB, Wa1 + (size_t)h * 128 * 256 + 128, 256, tid);
#pragma unroll
    for (int i = 0; i < 16; i++) {
        int v = i * 256 + tid;
        int r = v >> 5, c4 = v & 31;
        float4 val = reinterpret_cast<const float4*>(cry + (size_t)s0 * 128)[r * 32 + c4];
        uint2 u = make_uint2(h2pack(val.x, val.y), h2pack(val.z, val.w));
        *reinterpret_cast<uint2*>(sA + r * LH2 + c4 * 2) = u;
    }
    __syncthreads();

    float acc[2][8][4];
#pragma unroll
    for (int x1 = 0; x1 < 2; x1++)
#pragma unroll
        for (int x2 = 0; x2 < 8; x2++)
#pragma unroll
            for (int x3 = 0; x3 < 4; x3++) acc[x1][x2][x3] = 0.f;
    gemm128h(sA, sB, acc, warpRow, warpCol, lane);

#pragma unroll
    for (int mt = 0; mt < 2; mt++)
#pragma unroll
        for (int nt = 0; nt < 8; nt++)
#pragma unroll
            for (int j = 0; j < 2; j++) {
                int row = warpRow * 32 + mt * 16 + g + j * 8;
                int c0  = warpCol * 64 + nt * 8 + 2 * t;
                g_pre1[((size_t)h * SEGS + s0 + row) * 64 + (c0 >> 1)] =
                    h2pack(acc[mt][nt][j * 2 + 0], acc[mt][nt][j * 2 + 1]);
            }
}

// ---------------- kernel 1 (fused): alpha/e + e-weighted message accumulation -
__global__ void __launch_bounds__(256, 2)
k_am(const float* __restrict__ Wa1, const float* __restrict__ ba1,
     const float* __restrict__ Wa2, const float* __restrict__ ba2,
     const float* __restrict__ Wm1, const float* __restrict__ bm1,
     const int* __restrict__ index) {
    extern __shared__ unsigned smem_u[];
    unsigned* sA   = smem_u;                   // fea tile / staging
    unsigned* sW1a = sA + 128 * LH2;           // W_a1 left half
    unsigned* sW1m = sW1a + 128 * LH2;         // W_m1
    float* sb1a   = (float*)(sW1m + 128 * LH2);
    float* sw2    = sb1a + 128;
    float* sb1m   = sw2 + 128;
    float* sPart  = sb1m + 128;                // 256
    int*   sSeg   = (int*)(sPart + 256);       // 128

    const int tid  = threadIdx.x;
    const int lane = tid & 31;
    const int warp = tid >> 5;
    const int warpRow = warp >> 1, warpCol = warp & 1;
    const int g = lane >> 2, t = lane & 3;
    const int h = blockIdx.y;
    float* Hh = g_H + (size_t)h * SEGS * 128;
    const unsigned* preH = g_pre1 + (size_t)h * SEGS * 64;

    load_w_h(sW1a, Wa1 + (size_t)h * 128 * 256, 256, tid);
    load_w_h(sW1m, Wm1 + (size_t)h * 128 * 128, 128, tid);
    if (tid < 128) {
        sb1a[tid] = ba1[h * 128 + tid];
        sw2[tid]  = Wa2[h * 128 + tid];
        sb1m[tid] = bm1[h * 128 + tid];
    }
    const float ba2v = ba2[h];
    const unsigned sAaddr = (unsigned)__cvta_generic_to_shared(sA);

    int tile = blockIdx.x;
    load_tile_async(sAaddr, g_feah + (size_t)tile * 128 * 64, tid);

    for (; tile < NTILES; tile += gridDim.x) {
        const int row0 = tile * 128;
        const int rows = min(128, N_NODES - row0);
        const int rlast = row0 + rows - 1;

        int myseg = 0;
        if (tid < 128)
            myseg = (tid < rows) ? index[row0 + tid] : index[rlast];

        asm volatile("cp.async.wait_group 0;" ::: "memory");
        __syncthreads();                    // S1: fea ready; prev tile fully done
        if (tid < 128) sSeg[tid] = myseg;   // read only after later barriers

        // ---- GEMM_a ----
        float acc[2][8][4];
#pragma unroll
        for (int x1 = 0; x1 < 2; x1++)
#pragma unroll
            for (int x2 = 0; x2 < 8; x2++)
#pragma unroll
                for (int x3 = 0; x3 < 4; x3++) acc[x1][x2][x3] = 0.f;
        gemm128h(sA, sW1a, acc, warpRow, warpCol, lane);

        // ---- alpha epilogue: seg + pre1 read straight from global ----
        float p[2][2];
#pragma unroll
        for (int mt = 0; mt < 2; mt++) { p[mt][0] = 0.f; p[mt][1] = 0.f; }
#pragma unroll
        for (int mt = 0; mt < 2; mt++)
#pragma unroll
            for (int j = 0; j < 2; j++) {
                int r = warpRow * 32 + mt * 16 + g + j * 8;
                int sidx = index[(r < rows) ? (row0 + r) : rlast];
                const unsigned* pr = preH + (size_t)sidx * 64;
#pragma unroll
                for (int nt = 0; nt < 8; nt++) {
                    const int c0 = warpCol * 64 + nt * 8 + 2 * t;
                    unsigned pw = pr[c0 >> 1];
                    float2 pf = __half22float2(*reinterpret_cast<__half2*>(&pw));
                    float x0 = acc[mt][nt][j * 2 + 0] + pf.x + sb1a[c0];
                    float x1 = acc[mt][nt][j * 2 + 1] + pf.y + sb1a[c0 + 1];
                    x0 = (x0 >= 0.f) ? x0 : SLOPE * x0;
                    x1 = (x1 >= 0.f) ? x1 : SLOPE * x1;
                    p[mt][j] += x0 * sw2[c0] + x1 * sw2[c0 + 1];
                }
            }
#pragma unroll
        for (int mt = 0; mt < 2; mt++)
#pragma unroll
            for (int j = 0; j < 2; j++) {
                float v = p[mt][j];
                v += __shfl_xor_sync(0xffffffffu, v, 1);
                v += __shfl_xor_sync(0xffffffffu, v, 2);
                if ((lane & 3) == 0)
                    sPart[(warpRow * 32 + mt * 16 + g + j * 8) * 2 + warpCol] = v;
            }
        __syncthreads();                    // S2: sPart visible
        if (tid < rows) {
            float av = sPart[tid * 2] + sPart[tid * 2 + 1] + ba2v;
            atomicAdd(&g_denom[myseg * 4 + h], expf(av));
        }

        // ---- GEMM_m (sA still holds fea; sPart stays valid) ----
#pragma unroll
        for (int x1 = 0; x1 < 2; x1++)
#pragma unroll
            for (int x2 = 0; x2 < 8; x2++)
#pragma unroll
                for (int x3 = 0; x3 < 4; x3++) acc[x1][x2][x3] = 0.f;
        gemm128h(sA, sW1m, acc, warpRow, warpCol, lane);
        __syncthreads();                    // S3: fea reads done; sA reusable

        // ---- stage e * leaky(acc + b1m) into sA as half2 (e inline) ----
#pragma unroll
        for (int mt = 0; mt < 2; mt++)
#pragma unroll
            for (int ip = 0; ip < 2; ip++) {
                int row = warpRow * 32 + mt * 16 + g + ip * 8;
                float e = 0.f;
                if (row < rows)
                    e = expf(sPart[row * 2] + sPart[row * 2 + 1] + ba2v);
#pragma unroll
                for (int nt = 0; nt < 8; nt++) {
                    int c0 = warpCol * 64 + nt * 8 + 2 * t;
                    float x0 = acc[mt][nt][ip * 2 + 0] + sb1m[c0];
                    float x1 = acc[mt][nt][ip * 2 + 1] + sb1m[c0 + 1];
                    x0 = (x0 >= 0.f) ? x0 : SLOPE * x0;
                    x1 = (x1 >= 0.f) ? x1 : SLOPE * x1;
                    sA[row * LH2 + (c0 >> 1)] = h2pack(x0 * e, x1 * e);
                }
            }
        __syncthreads();                    // S4: staging visible

        // ---- segmented reduce: thread = column-pair (64) x row-quarter (4) ----
        {
            const int cp  = tid & 63;
            const int q   = tid >> 6;
            const int r0q = q * 32;
            float a0 = 0.f, a1 = 0.f;
            int cur = sSeg[r0q];
#pragma unroll 4
            for (int r = 0; r < 32; r++) {
                int s = sSeg[r0q + r];
                if (s != cur) {
                    atomicAdd(&Hh[(size_t)cur * 128 + 2 * cp],     a0);
                    atomicAdd(&Hh[(size_t)cur * 128 + 2 * cp + 1], a1);
                    a0 = 0.f; a1 = 0.f;
                    cur = s;
                }
                unsigned pw = sA[(r0q + r) * LH2 + cp];
                float2 pf = __half22float2(*reinterpret_cast<__half2*>(&pw));
                a0 += pf.x; a1 += pf.y;
            }
            atomicAdd(&Hh[(size_t)cur * 128 + 2 * cp],     a0);
            atomicAdd(&Hh[(size_t)cur * 128 + 2 * cp + 1], a1);
        }
        __syncthreads();                    // S5: staging reads done

        const int tn = tile + gridDim.x;
        if (tn < NTILES)
            load_tile_async(sAaddr, g_feah + (size_t)tn * 128 * 64, tid);
    }
}

// ---------------- kernel 2: out = W2 . (H/denom) + b2*ind  (split-N, occ 2) --
__global__ void __launch_bounds__(256, 2)
k_out(const float* __restrict__ Wm2, const float* __restrict__ bm2,
      float* __restrict__ out) {
    extern __shared__ unsigned smem_u[];
    unsigned* sA = smem_u;                 // H tile (fp16, normalized) [128]
    unsigned* sB = sA + 128 * LH2;         // W2 half [64 rows]
    float* sb2  = (float*)(sB + 64 * LH2);
    float* sInd = sb2 + 64;
    float* sRcp = sInd + 128;

    const int tid  = threadIdx.x;
    const int lane = tid & 31;
    const int warp = tid >> 5;
    const int warpRow = warp >> 1, warpCol = warp & 1;
    const int g = lane >> 2, t = lane & 3;
    const int h     = blockIdx.y;
    const int s0    = (blockIdx.x >> 1) * 128;
    const int ncol0 = (blockIdx.x & 1) * 64;

    load_w_h64(sB, Wm2 + ((size_t)h * 128 + ncol0) * 128, 128, tid);
    if (tid < 128) {
        float d = g_denom[(s0 + tid) * 4 + h];
        sInd[tid] = (d > 0.f) ? 1.f : 0.f;
        sRcp[tid] = 1.f / (d + 1e-16f);
        if (tid < 64) sb2[tid] = bm2[h * 128 + ncol0 + tid];
    }
    __syncthreads();
    // H tile load with per-row normalization
    {
        const float* src = g_H + ((size_t)h * SEGS + s0) * 128;
#pragma unroll
        for (int i = 0; i < 16; i++) {
            int v = i * 256 + tid;
            int r = v >> 5, c4 = v & 31;
            float4 val = reinterpret_cast<const float4*>(src)[r * 32 + c4];
            float sc = sRcp[r];
            uint2 u = make_uint2(h2pack(val.x * sc, val.y * sc),
                                 h2pack(val.z * sc, val.w * sc));
            *reinterpret_cast<uint2*>(sA + r * LH2 + c4 * 2) = u;
        }
    }
    __syncthreads();

    float acc[2][4][4];
#pragma unroll
    for (int x1 = 0; x1 < 2; x1++)
#pragma unroll
        for (int x2 = 0; x2 < 4; x2++)
#pragma unroll
            for (int x3 = 0; x3 < 4; x3++) acc[x1][x2][x3] = 0.f;
    gemm64h(sA, sB, acc, warpRow, warpCol, lane);

#pragma unroll
    for (int mt = 0; mt < 2; mt++)
#pragma unroll
        for (int nt = 0; nt < 4; nt++)
#pragma unroll
            for (int ip = 0; ip < 2; ip++) {
                int row = warpRow * 32 + mt * 16 + g + ip * 8;
                int c0 = warpCol * 32 + nt * 8 + 2 * t;
                float a = sInd[row];
                float2 v;
                v.x = acc[mt][nt][ip * 2 + 0] * a + sb2[c0] * a;
                v.y = acc[mt][nt][ip * 2 + 1] * a + sb2[c0 + 1] * a;
                *reinterpret_cast<float2*>(
                    out + (size_t)(s0 + row) * 512 + h * 128 + ncol0 + c0) = v;
            }
}

// ---------------- launch ----------------
extern "C" void kernel_launch(void* const* d_in, const int* in_sizes, int n_in,
                              void* d_out, int out_size) {
    (void)in_sizes; (void)n_in; (void)out_size;
    const float* fea = (const float*)d_in[0];
    const float* cry = (const float*)d_in[1];
    const float* Wm1 = (const float*)d_in[2];
    const float* bm1 = (const float*)d_in[3];
    const float* Wm2 = (const float*)d_in[4];
    const float* bm2 = (const float*)d_in[5];
    const float* Wa1 = (const float*)d_in[6];
    const float* ba1 = (const float*)d_in[7];
    const float* Wa2 = (const float*)d_in[8];
    const float* ba2 = (const float*)d_in[9];
    const int*   idx = (const int*)d_in[10];
    float* out = (float*)d_out;

    const size_t smem_prep = (size_t)(2 * 128 * LH2) * 4;
    const size_t smem_am   = (size_t)(3 * 128 * LH2 + 128 + 128 + 128 + 256 + 128) * 4;
    const size_t smem_out  = (size_t)(128 * LH2 + 64 * LH2 + 64 + 128 + 128) * 4;
    cudaFuncSetAttribute(k_prep, cudaFuncAttributeMaxDynamicSharedMemorySize, (int)smem_prep);
    cudaFuncSetAttribute(k_am,   cudaFuncAttributeMaxDynamicSharedMemorySize, (int)smem_am);
    cudaFuncSetAttribute(k_out,  cudaFuncAttributeMaxDynamicSharedMemorySize, (int)smem_out);

    k_prep<<<2048, 256, smem_prep>>>(cry, Wa1, fea);
    k_am<<<dim3(74, 4), 256, smem_am>>>(Wa1, ba1, Wa2, ba2, Wm1, bm1, idx);
    k_out<<<dim3(256, 4), 256, smem_out>>>(Wm2, bm2, out);
}